// round 7
// baseline (speedup 1.0000x reference)
#include <cuda_runtime.h>
#include <math.h>

#define B_     8
#define N_     10000
#define D_     16
#define E_     320000
#define EH_    32
#define EOUT_  30
#define NOUT_  64
#define BN_    (B_ * N_)

typedef unsigned long long ull;

// ---------------- constant-memory weights ----------------
__constant__ float c_W1[35 * EH_];
__constant__ float c_b1[EH_];
__constant__ float c_Wn[EOUT_ * NOUT_];
__constant__ float c_bn[NOUT_];
__constant__ float c_wind[4];   // wm0, wm1, ws0, ws1
__constant__ float c_norm[4];   // mean0, mean1, rstd0, rstd1 (copied post-finalize)

// ---------------- device scratch ----------------
__device__ double g_stats[4];
__device__ float  g_norm[4];
__device__ __align__(16) float g_xT[N_ * D_ * B_];       // [n][k][b], 5.12 MB
__device__ __align__(16) float g_agg[N_ * EOUT_ * B_];   // [n][o][b], 9.6 MB

__device__ __forceinline__ float sigmoidf(float v) {
    return 1.0f / (1.0f + __expf(-v));
}

__device__ __forceinline__ ull pack_f2(float lo, float hi) {
    ull r;
    asm("mov.b64 %0, {%1, %2};" : "=l"(r) : "f"(lo), "f"(hi));
    return r;
}
__device__ __forceinline__ void unpack_f2(ull v, float& lo, float& hi) {
    asm("mov.b64 {%0, %1}, %2;" : "=f"(lo), "=f"(hi) : "l"(v));
}
__device__ __forceinline__ ull fma_f2(ull a, ull b, ull c) {
    ull d;
    asm("fma.rn.f32x2 %0, %1, %2, %3;" : "=l"(d) : "l"(a), "l"(b), "l"(c));
    return d;
}
__device__ __forceinline__ void red_f32(float* p, float v) {
    asm volatile("red.global.add.f32 [%0], %1;" :: "l"(p), "f"(v) : "memory");
}

// ---------------- zero scratch ----------------
__global__ void zero_kernel() {
    const int total4 = (N_ * EOUT_ * B_) / 4;
    float4 z = make_float4(0.f, 0.f, 0.f, 0.f);
    for (int i = blockIdx.x * blockDim.x + threadIdx.x; i < total4;
         i += gridDim.x * blockDim.x) {
        ((float4*)g_agg)[i] = z;
    }
    if (blockIdx.x == 0 && threadIdx.x < 4) g_stats[threadIdx.x] = 0.0;
}

// ---------------- transpose x: [b][n][k] -> [n][k][b] ----------------
__global__ void __launch_bounds__(256) transpose_kernel(const float* __restrict__ x) {
    int gid = blockIdx.x * blockDim.x + threadIdx.x;  // over N*D*B
    if (gid >= N_ * D_ * B_) return;
    int b = gid & 7;
    int k = (gid >> 3) & 15;
    int n = gid >> 7;
    g_xT[gid] = x[((size_t)b * N_ + n) * D_ + k];
}

// ---------------- edge_attr mean/std (double precision) ----------------
__global__ void stats_kernel(const float* __restrict__ ea) {
    double s0 = 0.0, s1 = 0.0, q0 = 0.0, q1 = 0.0;
    for (int i = blockIdx.x * blockDim.x + threadIdx.x; i < E_;
         i += gridDim.x * blockDim.x) {
        float a = ea[2 * i];
        float b = ea[2 * i + 1];
        s0 += (double)a;
        s1 += (double)b;
        q0 += (double)a * (double)a;
        q1 += (double)b * (double)b;
    }
    for (int o = 16; o > 0; o >>= 1) {
        s0 += __shfl_down_sync(0xffffffffu, s0, o);
        s1 += __shfl_down_sync(0xffffffffu, s1, o);
        q0 += __shfl_down_sync(0xffffffffu, q0, o);
        q1 += __shfl_down_sync(0xffffffffu, q1, o);
    }
    if ((threadIdx.x & 31) == 0) {
        atomicAdd(&g_stats[0], s0);
        atomicAdd(&g_stats[1], s1);
        atomicAdd(&g_stats[2], q0);
        atomicAdd(&g_stats[3], q1);
    }
}

__global__ void finalize_kernel() {
    if (threadIdx.x == 0 && blockIdx.x == 0) {
        const double n = (double)E_;
        double v0 = (g_stats[2] - g_stats[0] * g_stats[0] / n) / (n - 1.0);
        double v1 = (g_stats[3] - g_stats[1] * g_stats[1] / n) / (n - 1.0);
        g_norm[0] = (float)(g_stats[0] / n);
        g_norm[1] = (float)(g_stats[1] / n);
        g_norm[2] = (float)(1.0 / sqrt(v0));
        g_norm[3] = (float)(1.0 / sqrt(v1));
    }
}

// ---------------- edge MLP + scatter (coalesced batch-inner layout) ----------
__global__ void __launch_bounds__(256, 4) edge_kernel(
    const int* __restrict__ ei, const float* __restrict__ ea,
    const float* __restrict__ W2, const float* __restrict__ b2)
{
    __shared__ __align__(16) float sW2t[EOUT_ * EH_];   // transposed [30][32]
    __shared__ float sb2[EOUT_];
    for (int i = threadIdx.x; i < EH_ * EOUT_; i += blockDim.x) {
        int j = i / EOUT_;
        int o = i % EOUT_;
        sW2t[o * EH_ + j] = W2[i];
    }
    if (threadIdx.x < EOUT_) sb2[threadIdx.x] = b2[threadIdx.x];
    __syncthreads();

    unsigned gid = blockIdx.x * blockDim.x + threadIdx.x;
    if (gid >= (unsigned)(E_) * B_) return;
    int e = gid >> 3;       // edge id (8 consecutive lanes share it)
    int b = gid & 7;        // batch id
    int src = ei[e];
    int tgt = ei[E_ + e];

    // coalesced gathers: 8 lanes of an edge read 32B contiguous per feature
    const float* xsp = g_xT + (size_t)src * (D_ * B_) + b;
    const float* xtp = g_xT + (size_t)tgt * (D_ * B_) + b;
    float xs[D_], xt[D_];
#pragma unroll
    for (int k = 0; k < D_; k++) xs[k] = xsp[k * B_];
#pragma unroll
    for (int k = 0; k < D_; k++) xt[k] = xtp[k * B_];

    float speed = fmaf(xs[14], c_wind[2], c_wind[0]);
    float dir   = fmaf(xs[15], c_wind[3], c_wind[1]);
    float cd    = ea[2 * e];
    float cdi   = ea[2 * e + 1];
    float theta = fabsf(cdi - dir);
    float ewt   = fmaxf(0.0f, 3.0f * speed * __cosf(theta) / cd);
    float ean0  = (cd  - c_norm[0]) * c_norm[2];
    float ean1  = (cdi - c_norm[1]) * c_norm[3];

    // ---- layer 1 in f32x2 ----
    ull h2[16];
    {
        const ulonglong2* pb = (const ulonglong2*)c_b1;
#pragma unroll
        for (int q = 0; q < 8; q++) {
            ulonglong2 v = pb[q];
            h2[2 * q]     = v.x;
            h2[2 * q + 1] = v.y;
        }
    }
#pragma unroll
    for (int k = 0; k < D_; k++) {
        ull f2 = pack_f2(xs[k], xs[k]);
        const ulonglong2* w = (const ulonglong2*)(c_W1 + k * EH_);
#pragma unroll
        for (int q = 0; q < 8; q++) {
            ulonglong2 wv = w[q];
            h2[2 * q]     = fma_f2(f2, wv.x, h2[2 * q]);
            h2[2 * q + 1] = fma_f2(f2, wv.y, h2[2 * q + 1]);
        }
    }
#pragma unroll
    for (int k = 0; k < D_; k++) {
        ull f2 = pack_f2(xt[k], xt[k]);
        const ulonglong2* w = (const ulonglong2*)(c_W1 + (D_ + k) * EH_);
#pragma unroll
        for (int q = 0; q < 8; q++) {
            ulonglong2 wv = w[q];
            h2[2 * q]     = fma_f2(f2, wv.x, h2[2 * q]);
            h2[2 * q + 1] = fma_f2(f2, wv.y, h2[2 * q + 1]);
        }
    }
    {
        ull e02 = pack_f2(ean0, ean0);
        ull e12 = pack_f2(ean1, ean1);
        ull ew2 = pack_f2(ewt,  ewt);
        const ulonglong2* w32 = (const ulonglong2*)(c_W1 + 32 * EH_);
        const ulonglong2* w33 = (const ulonglong2*)(c_W1 + 33 * EH_);
        const ulonglong2* w34 = (const ulonglong2*)(c_W1 + 34 * EH_);
#pragma unroll
        for (int q = 0; q < 8; q++) {
            ulonglong2 v0 = w32[q];
            ulonglong2 v1 = w33[q];
            ulonglong2 v2 = w34[q];
            h2[2 * q]     = fma_f2(e02, v0.x, h2[2 * q]);
            h2[2 * q + 1] = fma_f2(e02, v0.y, h2[2 * q + 1]);
            h2[2 * q]     = fma_f2(e12, v1.x, h2[2 * q]);
            h2[2 * q + 1] = fma_f2(e12, v1.y, h2[2 * q + 1]);
            h2[2 * q]     = fma_f2(ew2, v2.x, h2[2 * q]);
            h2[2 * q + 1] = fma_f2(ew2, v2.y, h2[2 * q + 1]);
        }
    }
#pragma unroll
    for (int i = 0; i < 16; i++) {
        float lo, hi;
        unpack_f2(h2[i], lo, hi);
        h2[i] = pack_f2(sigmoidf(lo), sigmoidf(hi));
    }

    // ---- layer 2: compute each output, scatter immediately (coalesced reds) ----
    float* at = g_agg + (size_t)tgt * (EOUT_ * B_) + b;
    float* as = g_agg + (size_t)src * (EOUT_ * B_) + b;
#pragma unroll
    for (int o = 0; o < EOUT_; o++) {
        ull acc2 = pack_f2(sb2[o], 0.0f);
        const ulonglong2* w = (const ulonglong2*)(sW2t + o * EH_);
#pragma unroll
        for (int q = 0; q < 8; q++) {
            ulonglong2 wv = w[q];
            acc2 = fma_f2(h2[2 * q],     wv.x, acc2);
            acc2 = fma_f2(h2[2 * q + 1], wv.y, acc2);
        }
        float lo, hi;
        unpack_f2(acc2, lo, hi);
        float ev = sigmoidf(lo + hi);
        red_f32(at + o * B_,  ev);
        red_f32(as + o * B_, -ev);
    }
}

// ---------------- node MLP ----------------
__global__ void __launch_bounds__(256) node_kernel(float* __restrict__ out)
{
    int t = blockIdx.x * blockDim.x + threadIdx.x;
    if (t >= BN_) return;
    int n = t >> 3;       // node
    int b = t & 7;        // batch (8 lanes per node -> coalesced agg reads)

    float a[EOUT_];
    const float* ag = g_agg + (size_t)n * (EOUT_ * B_) + b;
#pragma unroll
    for (int j = 0; j < EOUT_; j++) a[j] = ag[j * B_];

    float* op = out + ((size_t)b * N_ + n) * NOUT_;
#pragma unroll
    for (int o = 0; o < NOUT_; o += 8) {
        float acc[8];
#pragma unroll
        for (int t2 = 0; t2 < 8; t2++) acc[t2] = c_bn[o + t2];
#pragma unroll
        for (int j = 0; j < EOUT_; j++) {
            float aj = a[j];
#pragma unroll
            for (int t2 = 0; t2 < 8; t2++)
                acc[t2] = fmaf(aj, c_Wn[j * NOUT_ + o + t2], acc[t2]);
        }
        float4 r0 = make_float4(sigmoidf(acc[0]), sigmoidf(acc[1]),
                                sigmoidf(acc[2]), sigmoidf(acc[3]));
        float4 r1 = make_float4(sigmoidf(acc[4]), sigmoidf(acc[5]),
                                sigmoidf(acc[6]), sigmoidf(acc[7]));
        *(float4*)(op + o)     = r0;
        *(float4*)(op + o + 4) = r1;
    }
}

// ---------------- launch ----------------
extern "C" void kernel_launch(void* const* d_in, const int* in_sizes, int n_in,
                              void* d_out, int out_size) {
    const float* x  = (const float*)d_in[0];
    const int*   ei = (const int*)d_in[1];
    const float* ea = (const float*)d_in[2];
    const float* wm = (const float*)d_in[3];
    const float* ws = (const float*)d_in[4];
    const float* W1 = (const float*)d_in[5];
    const float* b1 = (const float*)d_in[6];
    const float* W2 = (const float*)d_in[7];
    const float* b2 = (const float*)d_in[8];
    const float* Wn = (const float*)d_in[9];
    const float* bn = (const float*)d_in[10];
    float* out = (float*)d_out;

    cudaMemcpyToSymbolAsync(c_W1, W1, 35 * EH_ * sizeof(float), 0,
                            cudaMemcpyDeviceToDevice, 0);
    cudaMemcpyToSymbolAsync(c_b1, b1, EH_ * sizeof(float), 0,
                            cudaMemcpyDeviceToDevice, 0);
    cudaMemcpyToSymbolAsync(c_Wn, Wn, EOUT_ * NOUT_ * sizeof(float), 0,
                            cudaMemcpyDeviceToDevice, 0);
    cudaMemcpyToSymbolAsync(c_bn, bn, NOUT_ * sizeof(float), 0,
                            cudaMemcpyDeviceToDevice, 0);
    cudaMemcpyToSymbolAsync(c_wind, wm, 2 * sizeof(float), 0,
                            cudaMemcpyDeviceToDevice, 0);
    cudaMemcpyToSymbolAsync(c_wind, ws, 2 * sizeof(float), 2 * sizeof(float),
                            cudaMemcpyDeviceToDevice, 0);

    zero_kernel<<<512, 256>>>();
    transpose_kernel<<<(N_ * D_ * B_ + 255) / 256, 256>>>(x);
    stats_kernel<<<256, 256>>>(ea);
    finalize_kernel<<<1, 32>>>();

    // stage the computed normalization into constant memory (D2D, capturable)
    void* normPtr = nullptr;
    cudaGetSymbolAddress(&normPtr, g_norm);
    cudaMemcpyToSymbolAsync(c_norm, normPtr, 4 * sizeof(float), 0,
                            cudaMemcpyDeviceToDevice, 0);

    edge_kernel<<<(E_ * B_) / 256, 256>>>(ei, ea, W2, b2);
    node_kernel<<<(BN_ + 255) / 256, 256>>>(out);
}

// round 8
// speedup vs baseline: 1.6361x; 1.6361x over previous
#include <cuda_runtime.h>
#include <math.h>

#define B_     8
#define N_     10000
#define D_     16
#define E_     320000
#define EH_    32
#define EOUT_  30
#define NOUT_  64
#define BN_    (B_ * N_)

typedef unsigned long long ull;

// ---------------- constant-memory weights ----------------
__constant__ float c_W1[35 * EH_];
__constant__ float c_b1[EH_];
__constant__ float c_Wn[EOUT_ * NOUT_];
__constant__ float c_bn[NOUT_];
__constant__ float c_wind[4];   // wm0, wm1, ws0, ws1
__constant__ float c_norm[4];   // mean0, mean1, rstd0, rstd1

// ---------------- device scratch ----------------
__device__ double g_stats[4];
__device__ float  g_norm[4];
__device__ __align__(16) float4 g_x4[N_ * 4 * B_];     // [n][q][b], q=feature quad, 5.12 MB
__device__ __align__(16) float4 g_agg4[N_ * 7 * B_];   // [n][g][b], g=output quad,  8.96 MB
__device__ __align__(8)  float2 g_agg2[N_ * B_];       // [n][b], outputs 28..29,    0.64 MB

__device__ __forceinline__ float sigmoidf(float v) {
    return 1.0f / (1.0f + __expf(-v));
}

__device__ __forceinline__ ull pack_f2(float lo, float hi) {
    ull r;
    asm("mov.b64 %0, {%1, %2};" : "=l"(r) : "f"(lo), "f"(hi));
    return r;
}
__device__ __forceinline__ void unpack_f2(ull v, float& lo, float& hi) {
    asm("mov.b64 {%0, %1}, %2;" : "=f"(lo), "=f"(hi) : "l"(v));
}
__device__ __forceinline__ ull fma_f2(ull a, ull b, ull c) {
    ull d;
    asm("fma.rn.f32x2 %0, %1, %2, %3;" : "=l"(d) : "l"(a), "l"(b), "l"(c));
    return d;
}
__device__ __forceinline__ void red_v4(float* p, float a, float b, float c, float d) {
    asm volatile("red.global.add.v4.f32 [%0], {%1, %2, %3, %4};"
                 :: "l"(p), "f"(a), "f"(b), "f"(c), "f"(d) : "memory");
}
__device__ __forceinline__ void red_v2(float* p, float a, float b) {
    asm volatile("red.global.add.v2.f32 [%0], {%1, %2};"
                 :: "l"(p), "f"(a), "f"(b) : "memory");
}

// ---------------- zero scratch ----------------
__global__ void zero_kernel() {
    float4 z4 = make_float4(0.f, 0.f, 0.f, 0.f);
    for (int i = blockIdx.x * blockDim.x + threadIdx.x; i < N_ * 7 * B_;
         i += gridDim.x * blockDim.x) {
        g_agg4[i] = z4;
    }
    for (int i = blockIdx.x * blockDim.x + threadIdx.x; i < N_ * B_;
         i += gridDim.x * blockDim.x) {
        g_agg2[i] = make_float2(0.f, 0.f);
    }
    if (blockIdx.x == 0 && threadIdx.x < 4) g_stats[threadIdx.x] = 0.0;
}

// ---------------- transpose x: [b][n][k] -> float4 [n][q][b] ----------------
__global__ void __launch_bounds__(256) transpose_kernel(const float* __restrict__ x) {
    int gid = blockIdx.x * blockDim.x + threadIdx.x;   // over N*4*B float4s
    if (gid >= N_ * 4 * B_) return;
    int b = gid & 7;
    int q = (gid >> 3) & 3;
    int n = gid >> 5;
    g_x4[gid] = *(const float4*)(x + ((size_t)b * N_ + n) * D_ + 4 * q);
}

// ---------------- edge_attr mean/std (double precision) ----------------
__global__ void stats_kernel(const float* __restrict__ ea) {
    double s0 = 0.0, s1 = 0.0, q0 = 0.0, q1 = 0.0;
    for (int i = blockIdx.x * blockDim.x + threadIdx.x; i < E_;
         i += gridDim.x * blockDim.x) {
        float a = ea[2 * i];
        float b = ea[2 * i + 1];
        s0 += (double)a;
        s1 += (double)b;
        q0 += (double)a * (double)a;
        q1 += (double)b * (double)b;
    }
    for (int o = 16; o > 0; o >>= 1) {
        s0 += __shfl_down_sync(0xffffffffu, s0, o);
        s1 += __shfl_down_sync(0xffffffffu, s1, o);
        q0 += __shfl_down_sync(0xffffffffu, q0, o);
        q1 += __shfl_down_sync(0xffffffffu, q1, o);
    }
    if ((threadIdx.x & 31) == 0) {
        atomicAdd(&g_stats[0], s0);
        atomicAdd(&g_stats[1], s1);
        atomicAdd(&g_stats[2], q0);
        atomicAdd(&g_stats[3], q1);
    }
}

__global__ void finalize_kernel() {
    if (threadIdx.x == 0 && blockIdx.x == 0) {
        const double n = (double)E_;
        double v0 = (g_stats[2] - g_stats[0] * g_stats[0] / n) / (n - 1.0);
        double v1 = (g_stats[3] - g_stats[1] * g_stats[1] / n) / (n - 1.0);
        g_norm[0] = (float)(g_stats[0] / n);
        g_norm[1] = (float)(g_stats[1] / n);
        g_norm[2] = (float)(1.0 / sqrt(v0));
        g_norm[3] = (float)(1.0 / sqrt(v1));
    }
}

// ---------------- edge MLP + scatter (coalesced vector ops) ----------
__global__ void __launch_bounds__(256) edge_kernel(
    const int* __restrict__ ei, const float* __restrict__ ea,
    const float* __restrict__ W2, const float* __restrict__ b2)
{
    __shared__ __align__(16) float sW2t[EOUT_ * EH_];   // transposed [30][32]
    __shared__ float sb2[EOUT_];
    for (int i = threadIdx.x; i < EH_ * EOUT_; i += blockDim.x) {
        int j = i / EOUT_;
        int o = i % EOUT_;
        sW2t[o * EH_ + j] = W2[i];
    }
    if (threadIdx.x < EOUT_) sb2[threadIdx.x] = b2[threadIdx.x];
    __syncthreads();

    unsigned gid = blockIdx.x * blockDim.x + threadIdx.x;
    if (gid >= (unsigned)(E_) * B_) return;
    int e = gid >> 3;       // edge id (8 consecutive lanes share it)
    int b = gid & 7;        // batch id
    int src = ei[e];
    int tgt = ei[E_ + e];

    float cd   = ea[2 * e];
    float cdi  = ea[2 * e + 1];
    float ean0 = (cd  - c_norm[0]) * c_norm[2];
    float ean1 = (cdi - c_norm[1]) * c_norm[3];

    // ---- layer 1 in f32x2 ----
    ull h2[16];
    {
        const ulonglong2* pb = (const ulonglong2*)c_b1;
#pragma unroll
        for (int q = 0; q < 8; q++) {
            ulonglong2 v = pb[q];
            h2[2 * q]     = v.x;
            h2[2 * q + 1] = v.y;
        }
    }

    float speed = 0.0f, dir = 0.0f;
    // src features: coalesced float4 gathers (8 lanes -> one 128B line)
    const float4* xs4 = g_x4 + (size_t)src * (4 * B_) + b;
#pragma unroll
    for (int q = 0; q < 4; q++) {
        float4 f = xs4[q * B_];
        if (q == 3) {
            speed = fmaf(f.z, c_wind[2], c_wind[0]);
            dir   = fmaf(f.w, c_wind[3], c_wind[1]);
        }
        float fv[4] = {f.x, f.y, f.z, f.w};
#pragma unroll
        for (int kk = 0; kk < 4; kk++) {
            ull f2 = pack_f2(fv[kk], fv[kk]);
            const ulonglong2* w = (const ulonglong2*)(c_W1 + (4 * q + kk) * EH_);
#pragma unroll
            for (int p = 0; p < 8; p++) {
                ulonglong2 wv = w[p];
                h2[2 * p]     = fma_f2(f2, wv.x, h2[2 * p]);
                h2[2 * p + 1] = fma_f2(f2, wv.y, h2[2 * p + 1]);
            }
        }
    }
    // tgt features
    const float4* xt4 = g_x4 + (size_t)tgt * (4 * B_) + b;
#pragma unroll
    for (int q = 0; q < 4; q++) {
        float4 f = xt4[q * B_];
        float fv[4] = {f.x, f.y, f.z, f.w};
#pragma unroll
        for (int kk = 0; kk < 4; kk++) {
            ull f2 = pack_f2(fv[kk], fv[kk]);
            const ulonglong2* w = (const ulonglong2*)(c_W1 + (16 + 4 * q + kk) * EH_);
#pragma unroll
            for (int p = 0; p < 8; p++) {
                ulonglong2 wv = w[p];
                h2[2 * p]     = fma_f2(f2, wv.x, h2[2 * p]);
                h2[2 * p + 1] = fma_f2(f2, wv.y, h2[2 * p + 1]);
            }
        }
    }
    // rows 32..34
    {
        float theta = fabsf(cdi - dir);
        float ewt   = fmaxf(0.0f, 3.0f * speed * __cosf(theta) / cd);
        ull e02 = pack_f2(ean0, ean0);
        ull e12 = pack_f2(ean1, ean1);
        ull ew2 = pack_f2(ewt,  ewt);
        const ulonglong2* w32 = (const ulonglong2*)(c_W1 + 32 * EH_);
        const ulonglong2* w33 = (const ulonglong2*)(c_W1 + 33 * EH_);
        const ulonglong2* w34 = (const ulonglong2*)(c_W1 + 34 * EH_);
#pragma unroll
        for (int p = 0; p < 8; p++) {
            ulonglong2 v0 = w32[p];
            ulonglong2 v1 = w33[p];
            ulonglong2 v2 = w34[p];
            h2[2 * p]     = fma_f2(e02, v0.x, h2[2 * p]);
            h2[2 * p + 1] = fma_f2(e02, v0.y, h2[2 * p + 1]);
            h2[2 * p]     = fma_f2(e12, v1.x, h2[2 * p]);
            h2[2 * p + 1] = fma_f2(e12, v1.y, h2[2 * p + 1]);
            h2[2 * p]     = fma_f2(ew2, v2.x, h2[2 * p]);
            h2[2 * p + 1] = fma_f2(ew2, v2.y, h2[2 * p + 1]);
        }
    }
#pragma unroll
    for (int i = 0; i < 16; i++) {
        float lo, hi;
        unpack_f2(h2[i], lo, hi);
        h2[i] = pack_f2(sigmoidf(lo), sigmoidf(hi));
    }

    // ---- layer 2: output quads, coalesced vector reductions ----
    float4* at4 = g_agg4 + (size_t)tgt * (7 * B_) + b;
    float4* as4 = g_agg4 + (size_t)src * (7 * B_) + b;
#pragma unroll
    for (int g = 0; g < 7; g++) {
        int o0 = 4 * g;
        float ev[4];
#pragma unroll
        for (int t = 0; t < 4; t++) {
            ull acc2 = pack_f2(sb2[o0 + t], 0.0f);
            const ulonglong2* w = (const ulonglong2*)(sW2t + (o0 + t) * EH_);
#pragma unroll
            for (int p = 0; p < 8; p++) {
                ulonglong2 wv = w[p];
                acc2 = fma_f2(h2[2 * p],     wv.x, acc2);
                acc2 = fma_f2(h2[2 * p + 1], wv.y, acc2);
            }
            float lo, hi;
            unpack_f2(acc2, lo, hi);
            ev[t] = sigmoidf(lo + hi);
        }
        red_v4((float*)(at4 + g * B_),  ev[0],  ev[1],  ev[2],  ev[3]);
        red_v4((float*)(as4 + g * B_), -ev[0], -ev[1], -ev[2], -ev[3]);
    }
    // outputs 28, 29 -> float2 region
    {
        float ev[2];
#pragma unroll
        for (int t = 0; t < 2; t++) {
            ull acc2 = pack_f2(sb2[28 + t], 0.0f);
            const ulonglong2* w = (const ulonglong2*)(sW2t + (28 + t) * EH_);
#pragma unroll
            for (int p = 0; p < 8; p++) {
                ulonglong2 wv = w[p];
                acc2 = fma_f2(h2[2 * p],     wv.x, acc2);
                acc2 = fma_f2(h2[2 * p + 1], wv.y, acc2);
            }
            float lo, hi;
            unpack_f2(acc2, lo, hi);
            ev[t] = sigmoidf(lo + hi);
        }
        red_v2((float*)(g_agg2 + (size_t)tgt * B_ + b),  ev[0],  ev[1]);
        red_v2((float*)(g_agg2 + (size_t)src * B_ + b), -ev[0], -ev[1]);
    }
}

// ---------------- node MLP ----------------
__global__ void __launch_bounds__(256) node_kernel(float* __restrict__ out)
{
    int t = blockIdx.x * blockDim.x + threadIdx.x;
    if (t >= BN_) return;
    int n = t >> 3;       // node
    int b = t & 7;        // batch (8 lanes per node -> coalesced agg reads)

    float a[EOUT_];
    const float4* ag = g_agg4 + (size_t)n * (7 * B_) + b;
#pragma unroll
    for (int g = 0; g < 7; g++) {
        float4 v = ag[g * B_];
        a[4 * g + 0] = v.x; a[4 * g + 1] = v.y;
        a[4 * g + 2] = v.z; a[4 * g + 3] = v.w;
    }
    {
        float2 v = g_agg2[(size_t)n * B_ + b];
        a[28] = v.x; a[29] = v.y;
    }

    float* op = out + ((size_t)b * N_ + n) * NOUT_;
#pragma unroll
    for (int o = 0; o < NOUT_; o += 8) {
        float acc[8];
#pragma unroll
        for (int t2 = 0; t2 < 8; t2++) acc[t2] = c_bn[o + t2];
#pragma unroll
        for (int j = 0; j < EOUT_; j++) {
            float aj = a[j];
#pragma unroll
            for (int t2 = 0; t2 < 8; t2++)
                acc[t2] = fmaf(aj, c_Wn[j * NOUT_ + o + t2], acc[t2]);
        }
        float4 r0 = make_float4(sigmoidf(acc[0]), sigmoidf(acc[1]),
                                sigmoidf(acc[2]), sigmoidf(acc[3]));
        float4 r1 = make_float4(sigmoidf(acc[4]), sigmoidf(acc[5]),
                                sigmoidf(acc[6]), sigmoidf(acc[7]));
        *(float4*)(op + o)     = r0;
        *(float4*)(op + o + 4) = r1;
    }
}

// ---------------- launch ----------------
extern "C" void kernel_launch(void* const* d_in, const int* in_sizes, int n_in,
                              void* d_out, int out_size) {
    const float* x  = (const float*)d_in[0];
    const int*   ei = (const int*)d_in[1];
    const float* ea = (const float*)d_in[2];
    const float* wm = (const float*)d_in[3];
    const float* ws = (const float*)d_in[4];
    const float* W1 = (const float*)d_in[5];
    const float* b1 = (const float*)d_in[6];
    const float* W2 = (const float*)d_in[7];
    const float* b2 = (const float*)d_in[8];
    const float* Wn = (const float*)d_in[9];
    const float* bn = (const float*)d_in[10];
    float* out = (float*)d_out;

    cudaMemcpyToSymbolAsync(c_W1, W1, 35 * EH_ * sizeof(float), 0,
                            cudaMemcpyDeviceToDevice, 0);
    cudaMemcpyToSymbolAsync(c_b1, b1, EH_ * sizeof(float), 0,
                            cudaMemcpyDeviceToDevice, 0);
    cudaMemcpyToSymbolAsync(c_Wn, Wn, EOUT_ * NOUT_ * sizeof(float), 0,
                            cudaMemcpyDeviceToDevice, 0);
    cudaMemcpyToSymbolAsync(c_bn, bn, NOUT_ * sizeof(float), 0,
                            cudaMemcpyDeviceToDevice, 0);
    cudaMemcpyToSymbolAsync(c_wind, wm, 2 * sizeof(float), 0,
                            cudaMemcpyDeviceToDevice, 0);
    cudaMemcpyToSymbolAsync(c_wind, ws, 2 * sizeof(float), 2 * sizeof(float),
                            cudaMemcpyDeviceToDevice, 0);

    zero_kernel<<<512, 256>>>();
    transpose_kernel<<<(N_ * 4 * B_ + 255) / 256, 256>>>(x);
    stats_kernel<<<256, 256>>>(ea);
    finalize_kernel<<<1, 32>>>();

    void* normPtr = nullptr;
    cudaGetSymbolAddress(&normPtr, g_norm);
    cudaMemcpyToSymbolAsync(c_norm, normPtr, 4 * sizeof(float), 0,
                            cudaMemcpyDeviceToDevice, 0);

    edge_kernel<<<(E_ * B_) / 256, 256>>>(ei, ea, W2, b2);
    node_kernel<<<(BN_ + 255) / 256, 256>>>(out);
}